// round 12
// baseline (speedup 1.0000x reference)
#include <cuda_runtime.h>
#include <cstdint>

#define B_  512
#define D_  1024
#define H1_ 512
#define H2_ 128

// scratch (device globals — no allocation allowed)
__device__ float g_c1[B_ * H1_];
__device__ float g_c3[B_ * H1_];

__device__ __forceinline__ float sigmoidf(float z) {
    return 1.0f / (1.0f + expf(-z));
}

// ---------------------------------------------------------------------------
// Generic fp32 tiled GEMM:  C = act(A @ op(B) + bias)
//   A: [M,K] row-major.  BT=true: B stored [N,K] (use B^T).  BT=false: B [K,N].
// ---------------------------------------------------------------------------
template<int BM, int BN, int BK, int TM, int TN, bool BT, bool SIG>
__global__ __launch_bounds__(256)
void gemm_kernel(const float* __restrict__ A, const float* __restrict__ Bm,
                 const float* __restrict__ bias, float* __restrict__ C,
                 int M, int N, int K)
{
    constexpr int ASTR = BM + 2;                 // conflict-free transposed STS
    constexpr int BSTR = BT ? (BN + 2) : (BN + 4); // non-BT rows 16B-aligned
    __shared__ float As[BK][ASTR];
    __shared__ float Bs[BK][BSTR];

    const int tid = threadIdx.x;
    constexpr int TX = BN / TN;
    const int tx = tid % TX, ty = tid / TX;
    const int bm = blockIdx.y * BM, bn = blockIdx.x * BN;

    float acc[TM][TN];
#pragma unroll
    for (int i = 0; i < TM; i++)
#pragma unroll
        for (int j = 0; j < TN; j++) acc[i][j] = 0.0f;

    for (int k0 = 0; k0 < K; k0 += BK) {
        // A tile: BM x BK, float4 along K, transpose into As[k][m]
        for (int i = tid; i < BM * BK / 4; i += 256) {
            int r = i / (BK / 4), c4 = i % (BK / 4);
            float4 v = *(const float4*)&A[(size_t)(bm + r) * K + k0 + c4 * 4];
            As[c4 * 4 + 0][r] = v.x; As[c4 * 4 + 1][r] = v.y;
            As[c4 * 4 + 2][r] = v.z; As[c4 * 4 + 3][r] = v.w;
        }
        if constexpr (BT) {
            for (int i = tid; i < BN * BK / 4; i += 256) {
                int r = i / (BK / 4), c4 = i % (BK / 4);
                float4 v = *(const float4*)&Bm[(size_t)(bn + r) * K + k0 + c4 * 4];
                Bs[c4 * 4 + 0][r] = v.x; Bs[c4 * 4 + 1][r] = v.y;
                Bs[c4 * 4 + 2][r] = v.z; Bs[c4 * 4 + 3][r] = v.w;
            }
        } else {
            for (int i = tid; i < BK * BN / 4; i += 256) {
                int r = i / (BN / 4), c4 = i % (BN / 4);
                *(float4*)&Bs[r][c4 * 4] =
                    *(const float4*)&Bm[(size_t)(k0 + r) * N + bn + c4 * 4];
            }
        }
        __syncthreads();

#pragma unroll
        for (int k = 0; k < BK; k++) {
            float a[TM], b[TN];
#pragma unroll
            for (int i = 0; i < TM; i++) a[i] = As[k][ty * TM + i];
#pragma unroll
            for (int j = 0; j < TN; j++) b[j] = Bs[k][tx * TN + j];
#pragma unroll
            for (int i = 0; i < TM; i++)
#pragma unroll
                for (int j = 0; j < TN; j++)
                    acc[i][j] = fmaf(a[i], b[j], acc[i][j]);
        }
        __syncthreads();
    }

#pragma unroll
    for (int i = 0; i < TM; i++) {
        int m = bm + ty * TM + i;
#pragma unroll
        for (int j = 0; j < TN; j++) {
            int n = bn + tx * TN + j;
            float v = acc[i][j] + bias[n];
            if (SIG) v = sigmoidf(v);
            C[(size_t)m * N + n] = v;
        }
    }
}

// ---------------------------------------------------------------------------
// Jacobian kernel: per (b, ntile) CTA computes
//   Jac[b, :, n0:n0+128] = diag(s2p[b]) * ((W2 .* s1p[b]) @ W1[:, n0:n0+128])
// via mma.sync m16n8k8 tf32.  CTA tile 128x128, K=512 in chunks of 32.
// ---------------------------------------------------------------------------
__device__ __forceinline__ uint32_t f2tf(float f) {
    uint32_t u;
    asm("cvt.rna.tf32.f32 %0, %1;" : "=r"(u) : "f"(f));
    return u;
}

__device__ __forceinline__ void mma_tf32(float d[4], const uint32_t a[4],
                                         uint32_t b0, uint32_t b1) {
    asm volatile(
        "mma.sync.aligned.m16n8k8.row.col.f32.tf32.tf32.f32 "
        "{%0,%1,%2,%3}, {%4,%5,%6,%7}, {%8,%9}, {%0,%1,%2,%3};"
        : "+f"(d[0]), "+f"(d[1]), "+f"(d[2]), "+f"(d[3])
        : "r"(a[0]), "r"(a[1]), "r"(a[2]), "r"(a[3]), "r"(b0), "r"(b1));
}

#define JP_A 133   // odd-ish pad: conflict-free transposed STS, <=2-way frag LDS
#define JP_B 132   // 16B-aligned rows for uint4 STS

__global__ __launch_bounds__(256, 2)
void jac_kernel(const float* __restrict__ W1, const float* __restrict__ W2,
                const float* __restrict__ c1, const float* __restrict__ c2,
                float* __restrict__ jac)
{
    __shared__ float s1p[H1_];
    __shared__ float s2p[H2_];
    __shared__ __align__(16) uint32_t As[32][JP_A];   // [k][h], tf32 bits
    __shared__ __align__(16) uint32_t Bs[32][JP_B];   // [k][n], tf32 bits

    const int tid = threadIdx.x;
    const int b   = blockIdx.y;
    const int n0  = blockIdx.x * 128;

    for (int i = tid; i < H1_; i += 256) {
        float v = c1[(size_t)b * H1_ + i];
        s1p[i] = v * (1.0f - v);
    }
    for (int i = tid; i < H2_; i += 256) {
        float v = c2[(size_t)b * H2_ + i];
        s2p[i] = v * (1.0f - v);
    }
    __syncthreads();

    const int lane  = tid & 31, wid = tid >> 5;
    const int mbase = (wid & 3) * 32;   // 4 warps along M (128 rows)
    const int nbase = (wid >> 2) * 64;  // 2 warps along N (128 cols)
    const int g = lane >> 2, tg = lane & 3;

    float acc[2][8][4];
#pragma unroll
    for (int mi = 0; mi < 2; mi++)
#pragma unroll
        for (int ni = 0; ni < 8; ni++)
#pragma unroll
            for (int r = 0; r < 4; r++) acc[mi][ni][r] = 0.0f;

    for (int k0 = 0; k0 < H1_; k0 += 32) {
        // A tile: W2[h, k0:k0+32] * s1p -> As[k][h]  (128x32)
#pragma unroll
        for (int ii = 0; ii < 4; ii++) {
            int i = tid + ii * 256;
            int h = i >> 3, c4 = i & 7;
            float4 w = *(const float4*)&W2[(size_t)h * H1_ + k0 + c4 * 4];
            int kk = c4 * 4;
            As[kk + 0][h] = f2tf(w.x * s1p[k0 + kk + 0]);
            As[kk + 1][h] = f2tf(w.y * s1p[k0 + kk + 1]);
            As[kk + 2][h] = f2tf(w.z * s1p[k0 + kk + 2]);
            As[kk + 3][h] = f2tf(w.w * s1p[k0 + kk + 3]);
        }
        // B tile: W1[k0:k0+32, n0:n0+128] -> Bs[k][n]
#pragma unroll
        for (int ii = 0; ii < 4; ii++) {
            int i = tid + ii * 256;
            int r = i >> 5, c4 = i & 31;
            float4 v = *(const float4*)&W1[(size_t)(k0 + r) * D_ + n0 + c4 * 4];
            uint4 u;
            u.x = f2tf(v.x); u.y = f2tf(v.y); u.z = f2tf(v.z); u.w = f2tf(v.w);
            *(uint4*)&Bs[r][c4 * 4] = u;
        }
        __syncthreads();

#pragma unroll
        for (int k8 = 0; k8 < 4; k8++) {
            const int k = k8 * 8;
            uint32_t a[2][4];
#pragma unroll
            for (int mi = 0; mi < 2; mi++) {
                int row = mbase + mi * 16 + g;
                a[mi][0] = As[k + tg][row];
                a[mi][1] = As[k + tg][row + 8];
                a[mi][2] = As[k + tg + 4][row];
                a[mi][3] = As[k + tg + 4][row + 8];
            }
#pragma unroll
            for (int ni = 0; ni < 8; ni++) {
                int col = nbase + ni * 8 + g;
                uint32_t b0 = Bs[k + tg][col];
                uint32_t b1 = Bs[k + tg + 4][col];
                mma_tf32(acc[0][ni], a[0], b0, b1);
                mma_tf32(acc[1][ni], a[1], b0, b1);
            }
        }
        __syncthreads();
    }

    // epilogue: scale rows by s2p, float2 stores (full 32B sectors)
    float* outb = jac + (size_t)b * (H2_ * D_) + n0;
#pragma unroll
    for (int mi = 0; mi < 2; mi++) {
        int r0 = mbase + mi * 16 + g;
        int r1 = r0 + 8;
        float s0 = s2p[r0], s1 = s2p[r1];
#pragma unroll
        for (int ni = 0; ni < 8; ni++) {
            int col = nbase + ni * 8 + tg * 2;
            float2 v0 = make_float2(acc[mi][ni][0] * s0, acc[mi][ni][1] * s0);
            float2 v1 = make_float2(acc[mi][ni][2] * s1, acc[mi][ni][3] * s1);
            *(float2*)&outb[(size_t)r0 * D_ + col] = v0;
            *(float2*)&outb[(size_t)r1 * D_ + col] = v1;
        }
    }
}

// ---------------------------------------------------------------------------
// launch: 5 kernels on the default stream (graph-capturable, no allocs)
// out layout (flattened tuple): recover[512*1024], c2[512*128], Jac[512*128*1024]
// ---------------------------------------------------------------------------
extern "C" void kernel_launch(void* const* d_in, const int* in_sizes, int n_in,
                              void* d_out, int out_size)
{
    (void)in_sizes; (void)n_in; (void)out_size;
    const float* x   = (const float*)d_in[0];
    const float* W1  = (const float*)d_in[1];
    const float* b1  = (const float*)d_in[2];
    const float* W2  = (const float*)d_in[3];
    const float* b2  = (const float*)d_in[4];
    const float* b3  = (const float*)d_in[5];
    const float* b_r = (const float*)d_in[6];

    float* out     = (float*)d_out;
    float* recover = out;                    // 512*1024
    float* c2o     = out + (size_t)B_ * D_;  // 512*128
    float* jac     = c2o + (size_t)B_ * H2_; // 512*128*1024

    float *c1p = nullptr, *c3p = nullptr;
    cudaGetSymbolAddress((void**)&c1p, g_c1);
    cudaGetSymbolAddress((void**)&c3p, g_c3);

    // c1 = sigmoid(x @ W1^T + b1)          [512,512] K=1024
    gemm_kernel<64, 64, 16, 4, 4, true, true>
        <<<dim3(H1_ / 64, B_ / 64), 256>>>(x, W1, b1, c1p, B_, H1_, D_);
    // c2 = sigmoid(c1 @ W2^T + b2)         [512,128] K=512  -> output region
    gemm_kernel<64, 32, 16, 4, 2, true, true>
        <<<dim3(H2_ / 32, B_ / 64), 256>>>(c1p, W2, b2, c2o, B_, H2_, H1_);
    // c3 = sigmoid(c2 @ W2 + b3)           [512,512] K=128
    gemm_kernel<64, 64, 16, 4, 4, false, true>
        <<<dim3(H1_ / 64, B_ / 64), 256>>>(c2o, W2, b3, c3p, B_, H1_, H2_);
    // recover = c3 @ W1 + b_r              [512,1024] K=512 -> output region
    gemm_kernel<64, 64, 16, 4, 4, false, false>
        <<<dim3(D_ / 64, B_ / 64), 256>>>(c3p, W1, b_r, recover, B_, D_, H1_);
    // Jac                                   [512,128,1024]
    jac_kernel<<<dim3(D_ / 128, B_), 256>>>(W1, W2, c1p, c2o, jac);
}

// round 16
// speedup vs baseline: 1.2629x; 1.2629x over previous
#include <cuda_runtime.h>
#include <cstdint>

#define B_  512
#define D_  1024
#define H1_ 512
#define H2_ 128

// scratch (device globals — no allocation allowed)
__device__ float g_c1[B_ * H1_];
__device__ float g_c3[B_ * H1_];

__device__ __forceinline__ float sigmoidf(float z) {
    return 1.0f / (1.0f + expf(-z));
}
__device__ __forceinline__ uint32_t f2tf(float f) {
    uint32_t u;
    asm("cvt.rna.tf32.f32 %0, %1;" : "=r"(u) : "f"(f));
    return u;
}
__device__ __forceinline__ uint32_t smem_u32(const void* p) {
    uint32_t a;
    asm("{ .reg .u64 t; cvta.to.shared.u64 t, %1; cvt.u32.u64 %0, t; }"
        : "=r"(a) : "l"(p));
    return a;
}
#define CP16(dst, src) \
    asm volatile("cp.async.cg.shared.global [%0], [%1], 16;" \
                 :: "r"(dst), "l"(src) : "memory")
#define CP_COMMIT() asm volatile("cp.async.commit_group;" ::: "memory")

__device__ __forceinline__ void mma_tf32(float d[4], const uint32_t a[4],
                                         uint32_t b0, uint32_t b1) {
    asm volatile(
        "mma.sync.aligned.m16n8k8.row.col.f32.tf32.tf32.f32 "
        "{%0,%1,%2,%3}, {%4,%5,%6,%7}, {%8,%9}, {%0,%1,%2,%3};"
        : "+f"(d[0]), "+f"(d[1]), "+f"(d[2]), "+f"(d[3])
        : "r"(a[0]), "r"(a[1]), "r"(a[2]), "r"(a[3]), "r"(b0), "r"(b1));
}

// ---------------------------------------------------------------------------
// fp32 tiled GEMM with register-prefetch double buffering.
//   A: [M,K] row-major.  BT: B stored [N,K] (use B^T) else [K,N].
// ---------------------------------------------------------------------------
template<int BM, int BN, int BK, int TM, int TN, bool BT, bool SIG>
__global__ __launch_bounds__(256)
void gemm_kernel(const float* __restrict__ A, const float* __restrict__ Bm,
                 const float* __restrict__ bias, float* __restrict__ C,
                 int M, int N, int K)
{
    constexpr int ASTR = BM + 2;
    constexpr int BSTR = BT ? (BN + 2) : (BN + 4);
    __shared__ float As[BK][ASTR];
    __shared__ float Bs[BK][BSTR];
    constexpr int LA = BM * BK / (4 * 256);
    constexpr int LB = BK * BN / (4 * 256);
    static_assert(LA >= 1 && LB >= 1, "tile too small");

    const int tid = threadIdx.x;
    constexpr int TX = BN / TN;
    const int tx = tid % TX, ty = tid / TX;
    const int bm = blockIdx.y * BM, bn = blockIdx.x * BN;

    float4 ra[LA], rb[LB];
    float acc[TM][TN];
#pragma unroll
    for (int i = 0; i < TM; i++)
#pragma unroll
        for (int j = 0; j < TN; j++) acc[i][j] = 0.0f;

#pragma unroll
    for (int l = 0; l < LA; l++) {
        int i = tid + l * 256, r = i / (BK / 4), c4 = i % (BK / 4);
        ra[l] = *(const float4*)&A[(size_t)(bm + r) * K + c4 * 4];
    }
#pragma unroll
    for (int l = 0; l < LB; l++) {
        int i = tid + l * 256;
        if constexpr (BT) {
            int r = i / (BK / 4), c4 = i % (BK / 4);
            rb[l] = *(const float4*)&Bm[(size_t)(bn + r) * K + c4 * 4];
        } else {
            int r = i / (BN / 4), c4 = i % (BN / 4);
            rb[l] = *(const float4*)&Bm[(size_t)r * N + bn + c4 * 4];
        }
    }

    for (int k0 = 0; k0 < K; k0 += BK) {
#pragma unroll
        for (int l = 0; l < LA; l++) {
            int i = tid + l * 256, r = i / (BK / 4), c4 = i % (BK / 4);
            As[c4 * 4 + 0][r] = ra[l].x; As[c4 * 4 + 1][r] = ra[l].y;
            As[c4 * 4 + 2][r] = ra[l].z; As[c4 * 4 + 3][r] = ra[l].w;
        }
#pragma unroll
        for (int l = 0; l < LB; l++) {
            int i = tid + l * 256;
            if constexpr (BT) {
                int r = i / (BK / 4), c4 = i % (BK / 4);
                Bs[c4 * 4 + 0][r] = rb[l].x; Bs[c4 * 4 + 1][r] = rb[l].y;
                Bs[c4 * 4 + 2][r] = rb[l].z; Bs[c4 * 4 + 3][r] = rb[l].w;
            } else {
                int r = i / (BN / 4), c4 = i % (BN / 4);
                *(float4*)&Bs[r][c4 * 4] = rb[l];
            }
        }
        __syncthreads();

        if (k0 + BK < K) {
            int kn = k0 + BK;
#pragma unroll
            for (int l = 0; l < LA; l++) {
                int i = tid + l * 256, r = i / (BK / 4), c4 = i % (BK / 4);
                ra[l] = *(const float4*)&A[(size_t)(bm + r) * K + kn + c4 * 4];
            }
#pragma unroll
            for (int l = 0; l < LB; l++) {
                int i = tid + l * 256;
                if constexpr (BT) {
                    int r = i / (BK / 4), c4 = i % (BK / 4);
                    rb[l] = *(const float4*)&Bm[(size_t)(bn + r) * K + kn + c4 * 4];
                } else {
                    int r = i / (BN / 4), c4 = i % (BN / 4);
                    rb[l] = *(const float4*)&Bm[(size_t)(kn + r) * N + bn + c4 * 4];
                }
            }
        }

#pragma unroll
        for (int k = 0; k < BK; k++) {
            float a[TM], b[TN];
#pragma unroll
            for (int i = 0; i < TM; i++) a[i] = As[k][ty * TM + i];
#pragma unroll
            for (int j = 0; j < TN; j++) b[j] = Bs[k][tx * TN + j];
#pragma unroll
            for (int i = 0; i < TM; i++)
#pragma unroll
                for (int j = 0; j < TN; j++)
                    acc[i][j] = fmaf(a[i], b[j], acc[i][j]);
        }
        __syncthreads();
    }

#pragma unroll
    for (int i = 0; i < TM; i++) {
        int m = bm + ty * TM + i;
#pragma unroll
        for (int j = 0; j < TN; j++) {
            int n = bn + tx * TN + j;
            float v = acc[i][j] + bias[n];
            if (SIG) v = sigmoidf(v);
            C[(size_t)m * N + n] = v;
        }
    }
}

// ---------------------------------------------------------------------------
// Jacobian kernel (mma.sync tf32, batch-grouped G=2, cp.async double buffer).
// CTA = (n-tile of 128, batch-pair). For each batch g:
//   D_g[128h x 128n] = diag(s2p[g]) ((W2 .* s1p[g]) @ W1[:, n0:n0+128])
// SMEM holds RAW W2/W1 chunks (batch-independent fills); s1p scaling applied
// at fragment-load time. Strides: A rows 144B (bank 4g+tg, conflict-free),
// B rows 544B (bank 8tg+g, conflict-free).
// ---------------------------------------------------------------------------
#define JG    2
#define JKC   32
#define JNCH  16                       // 512 / 32
#define SM_S1P 0                       // JG*512 floats  = 4096 B
#define SM_S2P 4096                    // JG*128 floats  = 1024 B
#define SM_A   5120                    // 2 stages * 128 rows * 144 B = 36864
#define SM_B   41984                   // 2 stages * 32 rows * 544 B = 34816
#define SM_TOT 76800
#define ASTG   18432
#define BSTG   17408

__device__ __forceinline__ void jac_issue(uint32_t smb,
                                          const float* __restrict__ W1,
                                          const float* __restrict__ W2,
                                          int tid, int n0, int k0, int buf)
{
    const uint32_t ab = smb + SM_A + buf * ASTG;
    const uint32_t bb = smb + SM_B + buf * BSTG;
#pragma unroll
    for (int it = 0; it < 4; it++) {
        int gi = tid + it * 256;       // 1024 granules: 128 rows x 8
        int r = gi >> 3, c = gi & 7;
        CP16(ab + r * 144 + c * 16, W2 + (size_t)r * H1_ + k0 + c * 4);
    }
#pragma unroll
    for (int it = 0; it < 4; it++) {
        int gi = tid + it * 256;       // 1024 granules: 32 rows x 32
        int r = gi >> 5, c = gi & 31;
        CP16(bb + r * 544 + c * 16, W1 + (size_t)(k0 + r) * D_ + n0 + c * 4);
    }
}

__global__ __launch_bounds__(256, 1)
void jac_kernel(const float* __restrict__ W1, const float* __restrict__ W2,
                const float* __restrict__ c1, const float* __restrict__ c2,
                float* __restrict__ jac)
{
    extern __shared__ char sm[];
    const uint32_t smb = smem_u32(sm);
    float* s1p = (float*)(sm + SM_S1P);
    float* s2p = (float*)(sm + SM_S2P);

    const int tid = threadIdx.x;
    const int n0  = blockIdx.x * 128;
    const int b0  = blockIdx.y * JG;

    // prefetch chunk 0 immediately
    jac_issue(smb, W1, W2, tid, n0, 0, 0);
    CP_COMMIT();

    for (int i = tid; i < JG * H1_; i += 256) {
        int g = i >> 9, k = i & 511;
        float v = c1[(size_t)(b0 + g) * H1_ + k];
        s1p[i] = v * (1.0f - v);
    }
    for (int i = tid; i < JG * H2_; i += 256) {
        int g = i >> 7, h = i & 127;
        float v = c2[(size_t)(b0 + g) * H2_ + h];
        s2p[i] = v * (1.0f - v);
    }

    const int lane = tid & 31, wid = tid >> 5;
    const int mbase = (wid & 3) * 32;     // 4 warps along M
    const int nbase = (wid >> 2) * 64;    // 2 warps along N
    const int gq = lane >> 2, tg = lane & 3;

    float acc[JG][2][8][4];
#pragma unroll
    for (int g = 0; g < JG; g++)
#pragma unroll
        for (int mi = 0; mi < 2; mi++)
#pragma unroll
            for (int ni = 0; ni < 8; ni++)
#pragma unroll
                for (int r = 0; r < 4; r++) acc[g][mi][ni][r] = 0.0f;

#pragma unroll 1
    for (int ci = 0; ci < JNCH; ci++) {
        const int buf = ci & 1;
        const int k0  = ci * JKC;

        if (ci + 1 < JNCH) {
            jac_issue(smb, W1, W2, tid, n0, k0 + JKC, buf ^ 1);
            CP_COMMIT();
            asm volatile("cp.async.wait_group 1;" ::: "memory");
        } else {
            asm volatile("cp.async.wait_group 0;" ::: "memory");
        }
        __syncthreads();

        const float* Af = (const float*)(sm + SM_A + buf * ASTG); // stride 36
        const float* Bf = (const float*)(sm + SM_B + buf * BSTG); // stride 136

#pragma unroll
        for (int k8 = 0; k8 < 4; k8++) {
            const int kk = k8 * 8;
            uint32_t bfr[8][2];
#pragma unroll
            for (int ni = 0; ni < 8; ni++) {
                int col = nbase + ni * 8 + gq;
                bfr[ni][0] = f2tf(Bf[(kk + tg) * 136 + col]);
                bfr[ni][1] = f2tf(Bf[(kk + tg + 4) * 136 + col]);
            }
#pragma unroll
            for (int g = 0; g < JG; g++) {
                const float sv0 = s1p[g * H1_ + k0 + kk + tg];
                const float sv1 = s1p[g * H1_ + k0 + kk + tg + 4];
                uint32_t afr[2][4];
#pragma unroll
                for (int mi = 0; mi < 2; mi++) {
                    int row = mbase + mi * 16 + gq;
                    float r0 = Af[row * 36 + kk + tg];
                    float r1 = Af[(row + 8) * 36 + kk + tg];
                    float r2 = Af[row * 36 + kk + tg + 4];
                    float r3 = Af[(row + 8) * 36 + kk + tg + 4];
                    afr[mi][0] = f2tf(r0 * sv0);
                    afr[mi][1] = f2tf(r1 * sv0);
                    afr[mi][2] = f2tf(r2 * sv1);
                    afr[mi][3] = f2tf(r3 * sv1);
                }
#pragma unroll
                for (int ni = 0; ni < 8; ni++) {
                    mma_tf32(acc[g][0][ni], afr[0], bfr[ni][0], bfr[ni][1]);
                    mma_tf32(acc[g][1][ni], afr[1], bfr[ni][0], bfr[ni][1]);
                }
            }
        }
        __syncthreads();
    }

    // epilogue: scale rows by s2p, float2 stores
#pragma unroll
    for (int g = 0; g < JG; g++) {
        float* outb = jac + (size_t)(b0 + g) * (H2_ * D_) + n0;
#pragma unroll
        for (int mi = 0; mi < 2; mi++) {
            int r0 = mbase + mi * 16 + gq;
            int r1 = r0 + 8;
            float s0 = s2p[g * H2_ + r0], s1 = s2p[g * H2_ + r1];
#pragma unroll
            for (int ni = 0; ni < 8; ni++) {
                int col = nbase + ni * 8 + tg * 2;
                float2 v0 = make_float2(acc[g][mi][ni][0] * s0,
                                        acc[g][mi][ni][1] * s0);
                float2 v1 = make_float2(acc[g][mi][ni][2] * s1,
                                        acc[g][mi][ni][3] * s1);
                *(float2*)&outb[(size_t)r0 * D_ + col] = v0;
                *(float2*)&outb[(size_t)r1 * D_ + col] = v1;
            }
        }
    }
}

// ---------------------------------------------------------------------------
// launch: 5 kernels, default stream (graph-capturable, no allocs)
// out layout: recover[512*1024], c2[512*128], Jac[512*128*1024]
// ---------------------------------------------------------------------------
extern "C" void kernel_launch(void* const* d_in, const int* in_sizes, int n_in,
                              void* d_out, int out_size)
{
    (void)in_sizes; (void)n_in; (void)out_size;
    const float* x   = (const float*)d_in[0];
    const float* W1  = (const float*)d_in[1];
    const float* b1  = (const float*)d_in[2];
    const float* W2  = (const float*)d_in[3];
    const float* b2  = (const float*)d_in[4];
    const float* b3  = (const float*)d_in[5];
    const float* b_r = (const float*)d_in[6];

    float* out     = (float*)d_out;
    float* recover = out;                    // 512*1024
    float* c2o     = out + (size_t)B_ * D_;  // 512*128
    float* jac     = c2o + (size_t)B_ * H2_; // 512*128*1024

    float *c1p = nullptr, *c3p = nullptr;
    cudaGetSymbolAddress((void**)&c1p, g_c1);
    cudaGetSymbolAddress((void**)&c3p, g_c3);

    cudaFuncSetAttribute(jac_kernel,
                         cudaFuncAttributeMaxDynamicSharedMemorySize, SM_TOT);

    // c1 = sigmoid(x @ W1^T + b1)          [512,512] K=1024
    gemm_kernel<32, 64, 32, 2, 4, true, true>
        <<<dim3(H1_ / 64, B_ / 32), 256>>>(x, W1, b1, c1p, B_, H1_, D_);
    // c2 = sigmoid(c1 @ W2^T + b2)         [512,128] K=512  -> output region
    gemm_kernel<32, 32, 32, 2, 2, true, true>
        <<<dim3(H2_ / 32, B_ / 32), 256>>>(c1p, W2, b2, c2o, B_, H2_, H1_);
    // c3 = sigmoid(c2 @ W2 + b3)           [512,512] K=128
    gemm_kernel<32, 64, 32, 2, 4, false, true>
        <<<dim3(H1_ / 64, B_ / 32), 256>>>(c2o, W2, b3, c3p, B_, H1_, H2_);
    // recover = c3 @ W1 + b_r              [512,1024] K=512 -> output region
    gemm_kernel<32, 64, 32, 2, 4, false, false>
        <<<dim3(D_ / 64, B_ / 32), 256>>>(c3p, W1, b_r, recover, B_, D_, H1_);
    // Jac via mma.sync tf32, G=2            [512,128,1024]
    jac_kernel<<<dim3(D_ / 128, B_ / JG), 256, SM_TOT>>>(W1, W2, c1p, c2o, jac);
}